// round 4
// baseline (speedup 1.0000x reference)
#include <cuda_runtime.h>

// LIF update: elementwise over N = 64*256*32*32 = 16,777,216 f32 elements.
// Inputs (metadata order): impulse, mem, refrac_until, spiketrain (values unused).
// Output: 4*N floats: [psp | mem_out | refrac_out | spiketrain_out].
//
// Round 4: R3 (streaming hints, max-occupancy shape) + 2 float4/thread
// processed SEQUENTIALLY (two disjoint load->compute->store segments so the
// live register set stays ~30 and occupancy holds at 64 warps/SM), grid
// halved to 8192 CTAs -> half the waves / block-start overhead.

__device__ __forceinline__ void lif_lane(float imp, float m, float ru,
                                         float& psp, float& mo, float& ro, float& so)
{
    const float TIME = 5.0f;
    const float REFRAC_RESET = 7.0f;   // TIME + TAU_REFRAC
    const float V_THRESH = 1.0f;
    const float LEAK_AMT = 0.1f;       // 0.1 * DT

    float mi = (ru > TIME) ? 0.0f : imp;
    float nm = m + mi;
    nm = (nm > 0.0f) ? nm - LEAK_AMT : nm;
    bool sp = (nm >= V_THRESH);
    psp = sp ? V_THRESH : 0.0f;
    mo  = sp ? 0.0f : nm;
    ro  = sp ? REFRAC_RESET : ru;
    so  = sp ? TIME : 0.0f;
}

__device__ __forceinline__ void lif_vec4(
    const float4* __restrict__ impulse,
    const float4* __restrict__ mem,
    const float4* __restrict__ refrac_until,
    float4* __restrict__ out_psp,
    float4* __restrict__ out_mem,
    float4* __restrict__ out_refrac,
    float4* __restrict__ out_spiketrain,
    int i)
{
    float4 imp = __ldcs(&impulse[i]);
    float4 m   = __ldcs(&mem[i]);
    float4 ru  = __ldcs(&refrac_until[i]);

    float4 psp, mo, ro, so;
    lif_lane(imp.x, m.x, ru.x, psp.x, mo.x, ro.x, so.x);
    lif_lane(imp.y, m.y, ru.y, psp.y, mo.y, ro.y, so.y);
    lif_lane(imp.z, m.z, ru.z, psp.z, mo.z, ro.z, so.z);
    lif_lane(imp.w, m.w, ru.w, psp.w, mo.w, ro.w, so.w);

    __stcs(&out_psp[i],        psp);
    __stcs(&out_mem[i],        mo);
    __stcs(&out_refrac[i],     ro);
    __stcs(&out_spiketrain[i], so);
}

__global__ void __launch_bounds__(256) spike_layer_kernel(
    const float4* __restrict__ impulse,
    const float4* __restrict__ mem,
    const float4* __restrict__ refrac_until,
    float4* __restrict__ out_psp,
    float4* __restrict__ out_mem,
    float4* __restrict__ out_refrac,
    float4* __restrict__ out_spiketrain,
    int n4)
{
    // Each CTA covers 2 * 256 contiguous float4s; thread t handles
    // base + t and base + 256 (both fully coalesced per warp).
    int base = blockIdx.x * (blockDim.x * 2) + threadIdx.x;

    if (base < n4)
        lif_vec4(impulse, mem, refrac_until,
                 out_psp, out_mem, out_refrac, out_spiketrain, base);

    int i2 = base + blockDim.x;
    if (i2 < n4)
        lif_vec4(impulse, mem, refrac_until,
                 out_psp, out_mem, out_refrac, out_spiketrain, i2);
}

extern "C" void kernel_launch(void* const* d_in, const int* in_sizes, int n_in,
                              void* d_out, int out_size)
{
    const float* impulse      = (const float*)d_in[0];
    const float* mem          = (const float*)d_in[1];
    const float* refrac_until = (const float*)d_in[2];
    // d_in[3] (spiketrain) values are unused by the reference math.

    int n = in_sizes[0];          // 16,777,216
    int n4 = n / 4;               // 4,194,304 = 2^22

    float* out = (float*)d_out;   // [psp | mem | refrac | spiketrain], each n floats

    int threads = 256;
    int per_cta = threads * 2;
    int blocks = (n4 + per_cta - 1) / per_cta;   // 8192

    spike_layer_kernel<<<blocks, threads>>>(
        (const float4*)impulse,
        (const float4*)mem,
        (const float4*)refrac_until,
        (float4*)(out),
        (float4*)(out + (size_t)n),
        (float4*)(out + (size_t)2 * n),
        (float4*)(out + (size_t)3 * n),
        n4);
}